// round 11
// baseline (speedup 1.0000x reference)
#include <cuda_runtime.h>
#include <cuda_fp16.h>
#include <cstdint>
typedef uint32_t u32;

#define XPP 648                       // half2 words per channel-pair plane (≡8 mod 32)
#define BW_OFF (14 * XPP)             // 9072
#define SMEM_WORDS (BW_OFF + 5184)
#define SMEM_BYTES (SMEM_WORDS * 4)   // 57024 B

__device__ __forceinline__ void mma16(float& d0, float& d1, float& d2, float& d3,
                                      u32 a0, u32 a1, u32 a2, u32 a3, u32 b0, u32 b1) {
    asm("mma.sync.aligned.m16n8k16.row.col.f32.f16.f16.f32 "
        "{%0,%1,%2,%3},{%4,%5,%6,%7},{%8,%9},{%0,%1,%2,%3};"
        : "+f"(d0), "+f"(d1), "+f"(d2), "+f"(d3)
        : "r"(a0), "r"(a1), "r"(a2), "r"(a3), "r"(b0), "r"(b1));
}

__device__ __forceinline__ u32 h2(float a, float b) {
    __half2 v = __floats2half2_rn(a, b);      // .x = a (low half)
    return *reinterpret_cast<u32*>(&v);
}

// out[b, n*32+cc, h, w] = sum_{c<16,kh,kw} x[b,(4cc-c)&127,(h-kh)&31,(w-kw)&31] * W[n,c,kh,kw]
// CTA = (g, h-quarter, b). Warp = one (h, m16 tile). M-row r -> w = 2r / 2(r-8)+1.
// One m16n8k16 fp16 mma covers a 16-channel band; A k-pairs are half2 channel pairs.
// kh body runs two jc-groups with only 3 A-planes (30 regs) live -> fits 64-reg cap.
__global__ __launch_bounds__(512, 2)
void fconv_mma(const float* __restrict__ x, const float* __restrict__ w,
               float* __restrict__ out)
{
    extern __shared__ u32 sm[];
    u32* xs = sm;                 // [cp<14][r<16][j<40] half2(x[2cp], x[2cp+1])
    u32* Bs = sm + BW_OFF;        // [tap][n<8][tq<4][u<2] half2(W k-pair)

    const int t = threadIdx.x;
    const int g = blockIdx.x & 7, hq = blockIdx.x >> 3, b = blockIdx.y;
    const int chb = (16 * g + 113) & 127;          // (16g - 15) mod 128
    const float* xb = x + (size_t)b * 131072;

    // ---- stage x channel-pairs, rows 8hq-8 .. 8hq+7, halo'd cols of 40 ----
    for (int i = t; i < 8960; i += 512) {
        int cp = i / 640, r2 = i % 640, r = r2 / 40, j = r2 % 40;
        int h = (8 * hq - 8 + r) & 31, wc = (j + 24) & 31;
        float f0 = xb[((chb + 2 * cp)     & 127) * 1024 + h * 32 + wc];
        float f1 = xb[((chb + 2 * cp + 1) & 127) * 1024 + h * 32 + wc];
        xs[cp * XPP + r * 40 + j] = h2(f0, f1);
    }
    // ---- stage B: Bs[((tap*8+n)*4+tq)*2+u] = half2(W[n][15-(8u+2tq)], W[n][14-8u-2tq])
    for (int i = t; i < 5184; i += 512) {
        int u = i & 1, tq = (i >> 1) & 3, n = (i >> 3) & 7, tap = i >> 6;
        int c0 = 15 - (8 * u + 2 * tq);
        Bs[i] = h2(w[n * 1296 + c0 * 81 + tap], w[n * 1296 + (c0 - 1) * 81 + tap]);
    }
    __syncthreads();

    const int lane = t & 31, wid = t >> 5, gq = lane >> 2, tq = lane & 3;
    const int hloc = wid & 7, mt = wid >> 3;
    const int h = 8 * hq + hloc;

    float acc[4][4];
    #pragma unroll
    for (int jc = 0; jc < 4; ++jc)
        #pragma unroll
        for (int q = 0; q < 4; ++q) acc[jc][q] = 0.f;

    #pragma unroll 1
    for (int kh = 0; kh < 9; ++kh) {
        const int rl = hloc + 8 - kh;                 // staged row, 0..15
        const u32* xrow = xs + rl * 40 + 2 * gq + 16 * mt;
        const u32* brow = Bs + kh * 9 * 64 + gq * 8 + tq * 2;

        #pragma unroll
        for (int grp = 0; grp < 2; ++grp) {
            // planes grp, grp+2, grp+4 (channel-pair cp = tq + 2*plane)
            u32 CH[3][10];
            #pragma unroll
            for (int pl = 0; pl < 3; ++pl) {
                const u32* p = xrow + (tq + 2 * (grp + 2 * pl)) * XPP;
                #pragma unroll
                for (int q = 0; q < 5; ++q) {
                    uint2 v = *(const uint2*)(p + 2 * q);
                    CH[pl][2 * q] = v.x; CH[pl][2 * q + 1] = v.y;
                }
            }
            #pragma unroll
            for (int kw = 0; kw < 9; ++kw) {
                uint2 bv = *(const uint2*)(brow + kw * 64);
                mma16(acc[grp][0], acc[grp][1], acc[grp][2], acc[grp][3],
                      CH[0][8 - kw], CH[0][9 - kw],
                      CH[1][8 - kw], CH[1][9 - kw], bv.x, bv.y);
                mma16(acc[grp + 2][0], acc[grp + 2][1], acc[grp + 2][2], acc[grp + 2][3],
                      CH[1][8 - kw], CH[1][9 - kw],
                      CH[2][8 - kw], CH[2][9 - kw], bv.x, bv.y);
            }
        }
    }

    // ---- store: rows (gq, gq+8) -> w = (2gq, 2gq+1) + 16mt; cols 2tq,2tq+1 ----
    #pragma unroll
    for (int jc = 0; jc < 4; ++jc) {
        const int cc = 4 * g + jc;
        const int w0 = 2 * gq + 16 * mt;
        #pragma unroll
        for (int d = 0; d < 2; ++d) {
            const int ch = (2 * tq + d) * 32 + cc;
            float2 s = make_float2(acc[jc][d], acc[jc][2 + d]);
            *(float2*)(out + (size_t)b * 262144 + (size_t)ch * 1024
                       + h * 32 + w0) = s;
        }
    }
}

extern "C" void kernel_launch(void* const* d_in, const int* in_sizes, int n_in,
                              void* d_out, int out_size)
{
    const float* x = (const float*)d_in[0];   // (32,128,32,32) f32
    const float* w = (const float*)d_in[1];   // (8,16,9,9) f32
    float* out = (float*)d_out;               // (32,256,32,32) f32

    cudaFuncSetAttribute(fconv_mma,
                         cudaFuncAttributeMaxDynamicSharedMemorySize, SMEM_BYTES);
    dim3 grid(32, 32);                        // (g, hq) x b  -> 1024 CTAs
    fconv_mma<<<grid, 512, SMEM_BYTES>>>(x, w, out);
}